// round 3
// baseline (speedup 1.0000x reference)
#include <cuda_runtime.h>
#include <cstdint>
#include <cstddef>

// Problem dims
#define BB   64
#define TT   2048
#define ID   1024
#define HD   1024
#define OD   512

// ---------------------------------------------------------------------------
// Scratch (static __device__ arrays: the sanctioned alloc-free workaround)
// ---------------------------------------------------------------------------
__device__ float    g_pre[(size_t)TT * BB * HD];   // [t][b][h]  pre-activations (512 MB)
__device__ float    g_part[2][8][BB * HD];         // double-buffered K-split partials (4 MB)
__device__ float    g_h[BB * HD];                  // final hidden state
__device__ unsigned g_cnt;                         // grid barrier arrival count
__device__ unsigned g_gen;                         // grid barrier generation

// Accurate tanh built from EX2 (avoids tanh.approx under fast-math: EX2 is
// ~2^-22 rel err, tanh.approx is ~6e-4 abs err which compounds over 2048 steps)
__device__ __forceinline__ float tanh_acc(float x) {
    float ax = fabsf(x);
    float e  = exp2f(ax * 2.885390081777927f);     // e^{2|x|}
    float r  = 1.0f - 2.0f / (e + 1.0f);
    return (x < 0.0f) ? -r : r;
}

// ---------------------------------------------------------------------------
// init: reset barrier state (runs first in the graph every replay)
// ---------------------------------------------------------------------------
__global__ void init_kernel() {
    if (threadIdx.x == 0) { g_cnt = 0u; g_gen = 0u; }
}

// ---------------------------------------------------------------------------
// Phase 1: pre[(t*BB+b)*HD + j] = sum_k x[b][t][k] * W_ih[j][k] + b_h[j]
// Classic 128x128x8 fp32 SGEMM, 8x8 thread tile, 256 threads.
// M = BB*TT = 131072 rows (row m = b*TT + t), N = HD, K = ID.
// ---------------------------------------------------------------------------
__global__ __launch_bounds__(256) void phase1_kernel(
    const float* __restrict__ X, const float* __restrict__ W,
    const float* __restrict__ bh)
{
    __shared__ float As[8][128];
    __shared__ float Bs[8][128];

    const int tid = threadIdx.x;
    const int bm  = blockIdx.x;       // 0..1023
    const int bn  = blockIdx.y;       // 0..7
    const int tx  = tid & 15;         // n-thread
    const int ty  = tid >> 4;         // m-thread
    const int lrow = tid >> 1;        // 0..127 (tile row to load)
    const int lk4  = (tid & 1) << 2;  // 0 or 4

    const float* Ag = X + (size_t)(bm * 128 + lrow) * ID + lk4;
    const float* Bg = W + (size_t)(bn * 128 + lrow) * ID + lk4;

    float acc[8][8];
#pragma unroll
    for (int i = 0; i < 8; ++i)
#pragma unroll
        for (int j = 0; j < 8; ++j) acc[i][j] = 0.0f;

    for (int kt = 0; kt < ID; kt += 8) {
        float4 av = *(const float4*)(Ag + kt);
        float4 bv = *(const float4*)(Bg + kt);
        __syncthreads();
        As[lk4 + 0][lrow] = av.x; As[lk4 + 1][lrow] = av.y;
        As[lk4 + 2][lrow] = av.z; As[lk4 + 3][lrow] = av.w;
        Bs[lk4 + 0][lrow] = bv.x; Bs[lk4 + 1][lrow] = bv.y;
        Bs[lk4 + 2][lrow] = bv.z; Bs[lk4 + 3][lrow] = bv.w;
        __syncthreads();
#pragma unroll
        for (int kk = 0; kk < 8; ++kk) {
            float a[8], b[8];
            *(float4*)(a)     = *(const float4*)&As[kk][ty * 8];
            *(float4*)(a + 4) = *(const float4*)&As[kk][ty * 8 + 4];
            *(float4*)(b)     = *(const float4*)&Bs[kk][tx * 8];
            *(float4*)(b + 4) = *(const float4*)&Bs[kk][tx * 8 + 4];
#pragma unroll
            for (int i = 0; i < 8; ++i)
#pragma unroll
                for (int j = 0; j < 8; ++j)
                    acc[i][j] = fmaf(a[i], b[j], acc[i][j]);
        }
    }

    // Epilogue: remap row m=(b*TT+t) -> t-major layout, add bias.
    const int col0 = bn * 128 + tx * 8;
    float bb[8];
#pragma unroll
    for (int j = 0; j < 8; ++j) bb[j] = bh[col0 + j];
#pragma unroll
    for (int i = 0; i < 8; ++i) {
        int m  = bm * 128 + ty * 8 + i;
        int b_ = m >> 11;            // / TT
        int t_ = m & (TT - 1);       // % TT
        float* o = g_pre + ((size_t)t_ * BB + b_) * HD + col0;
#pragma unroll
        for (int j = 0; j < 8; ++j) o[j] = acc[i][j] + bb[j];
    }
}

// ---------------------------------------------------------------------------
// Phase 2: persistent recurrence kernel.
// 128 CTAs = 4 batch-groups(16) x 4 col-groups(256) x 8 K-splits(128).
// Each CTA keeps its W_hh slice [256 cols x 128 k] resident in SMEM (128 KB).
// Per step: (a) rebuild its h_t slice [16 b x 128 k] from last step's partials
// + pre (redundant across col-groups, avoids a 2nd barrier), (b) GEMM partial
// C[16x256] += H[16x128] * W[256x128]^T, (c) store to partial slab, (d) grid
// barrier.
// ---------------------------------------------------------------------------
#define RK_NCTA 128
#define RK_SMEM_BYTES ((128 * 256 + 128 * 16) * 4)   // 139264

__global__ __launch_bounds__(128) void recur_kernel(const float* __restrict__ Whh)
{
    extern __shared__ float smem[];
    float* Ws = smem;               // [k=128][n=256]  Ws[k*256+n] = W_hh[cg*256+n][ks*128+k]
    float* Hs = smem + 128 * 256;   // [k=128][m=16]   Hs[k*16+m]

    const int tid = threadIdx.x;    // 128 threads
    const int cta = blockIdx.x;
    const int bg  = cta & 3;
    const int cg  = (cta >> 2) & 3;
    const int ks  = cta >> 4;       // 0..7

    // Persistent W slice load (once per kernel)
    for (int e = tid; e < 128 * 256; e += 128) {
        int n = e >> 7, k = e & 127;
        Ws[k * 256 + n] = Whh[(size_t)(cg * 256 + n) * HD + (ks * 128 + k)];
    }
    __syncthreads();

    const int tm = tid >> 6;        // 0..1  (8 batches each)
    const int tn = tid & 63;        // 0..63 (4 cols each)
    const float4* Ws4 = (const float4*)Ws;

    for (int t = 0; t < TT; ++t) {
        const int p = t & 1;

        // --- (a) rebuild h_t slice ---
        if (t == 0) {
            for (int e = tid; e < 2048; e += 128) Hs[e] = 0.0f;
        } else {
            const float* pre = g_pre + (size_t)(t - 1) * BB * HD;
            const int q = 1 - p;
            for (int e = tid; e < 2048; e += 128) {
                int m = e >> 7, k = e & 127;
                size_t idx = (size_t)(bg * 16 + m) * HD + (size_t)(ks * 128 + k);
                float s = pre[idx];
#pragma unroll
                for (int sp = 0; sp < 8; ++sp) s += g_part[q][sp][idx];
                Hs[k * 16 + m] = tanh_acc(s);
            }
        }
        __syncthreads();

        // --- (b) GEMM partial: 8x4 thread tile over K=128 ---
        float acc[8][4];
#pragma unroll
        for (int i = 0; i < 8; ++i)
#pragma unroll
            for (int j = 0; j < 4; ++j) acc[i][j] = 0.0f;

#pragma unroll 4
        for (int k = 0; k < 128; ++k) {
            float4 wv = Ws4[(k << 6) + tn];
            const float* hp = &Hs[(k << 4) + (tm << 3)];
            float4 ha = *(const float4*)(hp);
            float4 hb = *(const float4*)(hp + 4);
            float hv[8] = {ha.x, ha.y, ha.z, ha.w, hb.x, hb.y, hb.z, hb.w};
            float wf[4] = {wv.x, wv.y, wv.z, wv.w};
#pragma unroll
            for (int i = 0; i < 8; ++i)
#pragma unroll
                for (int j = 0; j < 4; ++j)
                    acc[i][j] = fmaf(hv[i], wf[j], acc[i][j]);
        }

        // --- (c) store partials (coalesced float4) ---
        float* po = g_part[p][ks] + (size_t)(bg * 16 + tm * 8) * HD + cg * 256 + tn * 4;
#pragma unroll
        for (int i = 0; i < 8; ++i) {
            float4 v = make_float4(acc[i][0], acc[i][1], acc[i][2], acc[i][3]);
            *(float4*)(po + (size_t)i * HD) = v;
        }

        // --- (d) grid barrier (generation based; all 128 CTAs co-resident) ---
        __threadfence();
        __syncthreads();
        if (tid == 0) {
            unsigned target = *((volatile unsigned*)&g_gen) + 1u;
            unsigned prev   = atomicAdd(&g_cnt, 1u);
            if (prev == RK_NCTA - 1) {
                g_cnt = 0u;
                __threadfence();
                *((volatile unsigned*)&g_gen) = target;
            } else {
                while (*((volatile unsigned*)&g_gen) < target) { }
            }
            __threadfence();
        }
        __syncthreads();
    }

    // Final h_T = tanh(pre[T-1] + sum partials) -> g_h   (ks==0 CTAs, 16x256 each)
    if (ks == 0) {
        const float* pre = g_pre + (size_t)(TT - 1) * BB * HD;
        const int q = (TT - 1) & 1;   // = 1
        for (int e = tid; e < 16 * 256; e += 128) {
            int m = e >> 8, c = e & 255;
            size_t idx = (size_t)(bg * 16 + m) * HD + (size_t)(cg * 256 + c);
            float s = pre[idx];
#pragma unroll
            for (int sp = 0; sp < 8; ++sp) s += g_part[q][sp][idx];
            g_h[idx] = tanh_acc(s);
        }
    }
}

// ---------------------------------------------------------------------------
// Phase 3: out[b][o] = h_T[b] . W_out[o] + b_out[o]
// ---------------------------------------------------------------------------
__global__ __launch_bounds__(256) void out_kernel(
    const float* __restrict__ Wout, const float* __restrict__ bout,
    float* __restrict__ out)
{
    __shared__ float hs[HD];
    const int b = blockIdx.x, tid = threadIdx.x;
    for (int i = tid; i < HD; i += 256) hs[i] = g_h[(size_t)b * HD + i];
    __syncthreads();
    for (int o = tid; o < OD; o += 256) {
        const float* w = Wout + (size_t)o * HD;
        float s0 = 0.f, s1 = 0.f, s2 = 0.f, s3 = 0.f;
        for (int k = 0; k < HD; k += 4) {
            float4 wv = *(const float4*)(w + k);
            s0 = fmaf(hs[k + 0], wv.x, s0);
            s1 = fmaf(hs[k + 1], wv.y, s1);
            s2 = fmaf(hs[k + 2], wv.z, s2);
            s3 = fmaf(hs[k + 3], wv.w, s3);
        }
        out[(size_t)b * OD + o] = (s0 + s1) + (s2 + s3) + bout[o];
    }
}

// ---------------------------------------------------------------------------
extern "C" void kernel_launch(void* const* d_in, const int* in_sizes, int n_in,
                              void* d_out, int out_size)
{
    (void)in_sizes; (void)n_in; (void)out_size;
    const float* x    = (const float*)d_in[0];
    const float* Wih  = (const float*)d_in[1];
    const float* Whh  = (const float*)d_in[2];
    const float* bh   = (const float*)d_in[3];
    const float* Wout = (const float*)d_in[4];
    const float* bout = (const float*)d_in[5];
    float* out = (float*)d_out;

    // Opt-in to 136 KB dynamic SMEM for the persistent kernel (idempotent,
    // not a stream op, no allocation).
    cudaFuncSetAttribute(recur_kernel,
                         cudaFuncAttributeMaxDynamicSharedMemorySize,
                         RK_SMEM_BYTES);

    init_kernel<<<1, 32>>>();

    dim3 g1(1024, 8);                       // (M/128, HD/128)
    phase1_kernel<<<g1, 256>>>(x, Wih, bh);

    recur_kernel<<<RK_NCTA, 128, RK_SMEM_BYTES>>>(Whh);

    out_kernel<<<BB, 256>>>(Wout, bout, out);
}